// round 1
// baseline (speedup 1.0000x reference)
#include <cuda_runtime.h>

#define TT    8192
#define OBSN  512
#define HIDN  2048
#define NOBJN 8
#define CH    64
#define NCH   128   // TT / CH

// ---------------- scratch (device globals; no allocation allowed) ----------
__device__ float g_Abar[TT * HIDN];
__device__ float g_Bx  [TT * HIDN];
__device__ float g_C   [TT * HIDN];
__device__ float g_y   [TT * HIDN];
__device__ float g_P    [NCH * HIDN];
__device__ float g_E    [NCH * HIDN];
__device__ float g_carry[NCH * HIDN];

// ---------------- K1: fused 4-projection GEMM + SSM-parameter epilogue -----
// out(t,h) for 4 mats = sum_k x[t,k] * W[h,k]; epilogue:
//   A_bar = exp(sigmoid(delta_raw) * (-exp(A_log[h])))
//   Bx    = B * x_state
//   C     = C
#define BM 128
#define BN 32
#define BK 32

__global__ __launch_bounds__(256, 2)
void proj_kernel(const float* __restrict__ x,
                 const float* __restrict__ Win,
                 const float* __restrict__ Wb,
                 const float* __restrict__ Wc,
                 const float* __restrict__ Wd,
                 const float* __restrict__ Alog)
{
    __shared__ float xs[BK][BM + 4];
    __shared__ float ws[4][BK][BN + 1];

    const int tid = threadIdx.x;
    const int t0  = blockIdx.y * BM;
    const int h0  = blockIdx.x * BN;
    const float* Wm[4] = {Win, Wb, Wc, Wd};

    float acc[4][8][2];
#pragma unroll
    for (int m = 0; m < 4; m++)
#pragma unroll
        for (int i = 0; i < 8; i++) {
            acc[m][i][0] = 0.f; acc[m][i][1] = 0.f;
        }

    const int tm = tid >> 4;    // 0..15, covers 8 rows each
    const int tn = tid & 15;    // 0..15, covers 2 cols each
    const float4* x4 = (const float4*)x;

    for (int k0 = 0; k0 < OBSN; k0 += BK) {
        __syncthreads();
        // load x tile [BM x BK] transposed into xs[k][m]
#pragma unroll
        for (int r = 0; r < 4; r++) {
            int lin = tid + r * 256;        // float4 granularity, 1024 total
            int row = lin >> 3;             // 0..127
            int c4  = lin & 7;              // 0..7
            float4 v = x4[(size_t)(t0 + row) * (OBSN / 4) + (k0 >> 2) + c4];
            xs[c4 * 4 + 0][row] = v.x;
            xs[c4 * 4 + 1][row] = v.y;
            xs[c4 * 4 + 2][row] = v.z;
            xs[c4 * 4 + 3][row] = v.w;
        }
        // load 4 weight tiles [BN x BK] transposed into ws[m][k][n]
        {
            int row = tid >> 3;   // 0..31 (h within tile)
            int c4  = tid & 7;    // 0..7
#pragma unroll
            for (int m = 0; m < 4; m++) {
                const float4* w4 = (const float4*)Wm[m];
                float4 v = w4[(size_t)(h0 + row) * (OBSN / 4) + (k0 >> 2) + c4];
                ws[m][c4 * 4 + 0][row] = v.x;
                ws[m][c4 * 4 + 1][row] = v.y;
                ws[m][c4 * 4 + 2][row] = v.z;
                ws[m][c4 * 4 + 3][row] = v.w;
            }
        }
        __syncthreads();

#pragma unroll
        for (int kk = 0; kk < BK; kk++) {
            float xr[8];
#pragma unroll
            for (int i = 0; i < 8; i++) xr[i] = xs[kk][tm * 8 + i];
            float wr[4][2];
#pragma unroll
            for (int m = 0; m < 4; m++) {
                wr[m][0] = ws[m][kk][tn * 2 + 0];
                wr[m][1] = ws[m][kk][tn * 2 + 1];
            }
#pragma unroll
            for (int m = 0; m < 4; m++)
#pragma unroll
                for (int i = 0; i < 8; i++) {
                    acc[m][i][0] += xr[i] * wr[m][0];
                    acc[m][i][1] += xr[i] * wr[m][1];
                }
        }
    }

    // epilogue
    float aA[2];
#pragma unroll
    for (int j = 0; j < 2; j++)
        aA[j] = -expf(Alog[h0 + tn * 2 + j]);

#pragma unroll
    for (int i = 0; i < 8; i++) {
#pragma unroll
        for (int j = 0; j < 2; j++) {
            int t = t0 + tm * 8 + i;
            int h = h0 + tn * 2 + j;
            size_t idx = (size_t)t * HIDN + h;
            float xst = acc[0][i][j];
            float bb  = acc[1][i][j];
            float cc  = acc[2][i][j];
            float dr  = acc[3][i][j];
            float delta = 1.f / (1.f + expf(-dr));
            g_Abar[idx] = expf(delta * aA[j]);
            g_Bx[idx]   = bb * xst;
            g_C[idx]    = cc;
        }
    }
}

// ---------------- K2: per-chunk scan with zero init -> (P, E) --------------
__global__ __launch_bounds__(256)
void chunk_scan_kernel()
{
    int h = blockIdx.y * 256 + threadIdx.x;
    int c = blockIdx.x;
    float P = 1.f, E = 0.f;
    size_t base = (size_t)c * CH * HIDN + h;
#pragma unroll 4
    for (int i = 0; i < CH; i++) {
        float a  = g_Abar[base + (size_t)i * HIDN];
        float bx = g_Bx  [base + (size_t)i * HIDN];
        E = a * E + bx;
        P *= a;
    }
    g_P[(size_t)c * HIDN + h] = P;
    g_E[(size_t)c * HIDN + h] = E;
}

// ---------------- K3: serial chunk combine -> per-chunk carry-in -----------
__global__ __launch_bounds__(256)
void chunk_combine_kernel()
{
    int h = blockIdx.x * 256 + threadIdx.x;
    float H = 0.f;
    for (int c = 0; c < NCH; c++) {
        g_carry[(size_t)c * HIDN + h] = H;
        H = g_P[(size_t)c * HIDN + h] * H + g_E[(size_t)c * HIDN + h];
    }
}

// ---------------- K4: re-scan with carry, y = C * h ------------------------
__global__ __launch_bounds__(256)
void scan_apply_kernel()
{
    int h = blockIdx.y * 256 + threadIdx.x;
    int c = blockIdx.x;
    float H = g_carry[(size_t)c * HIDN + h];
    size_t base = (size_t)c * CH * HIDN + h;
#pragma unroll 4
    for (int i = 0; i < CH; i++) {
        size_t idx = base + (size_t)i * HIDN;
        float a = g_Abar[idx];
        H = a * H + g_Bx[idx];
        g_y[idx] = g_C[idx] * H;
    }
}

// ---------------- K5: out = y @ W_out^T + b_out + x @ W_skip^T -------------
__global__ __launch_bounds__(256)
void out_kernel(const float* __restrict__ x,
                const float* __restrict__ Wout,
                const float* __restrict__ bout,
                const float* __restrict__ Wskip,
                float* __restrict__ out)
{
    int t  = blockIdx.x;
    int tx = threadIdx.x;
    float p[NOBJN];
#pragma unroll
    for (int j = 0; j < NOBJN; j++) p[j] = 0.f;

    for (int h = tx; h < HIDN; h += 256) {
        float yv = g_y[(size_t)t * HIDN + h];
#pragma unroll
        for (int j = 0; j < NOBJN; j++)
            p[j] += yv * Wout[(size_t)j * HIDN + h];
    }
    for (int k = tx; k < OBSN; k += 256) {
        float xv = x[(size_t)t * OBSN + k];
#pragma unroll
        for (int j = 0; j < NOBJN; j++)
            p[j] += xv * Wskip[(size_t)j * OBSN + k];
    }

    // warp butterfly reduce each of 8 partials
#pragma unroll
    for (int off = 16; off > 0; off >>= 1)
#pragma unroll
        for (int j = 0; j < NOBJN; j++)
            p[j] += __shfl_xor_sync(0xffffffffu, p[j], off);

    __shared__ float s[NOBJN];
    if (tx < NOBJN) s[tx] = 0.f;
    __syncthreads();
    if ((tx & 31) == 0) {
#pragma unroll
        for (int j = 0; j < NOBJN; j++)
            atomicAdd(&s[j], p[j]);
    }
    __syncthreads();
    if (tx < NOBJN)
        out[(size_t)t * NOBJN + tx] = s[tx] + bout[tx];
}

// ---------------- launch ---------------------------------------------------
extern "C" void kernel_launch(void* const* d_in, const int* in_sizes, int n_in,
                              void* d_out, int out_size)
{
    const float* x     = (const float*)d_in[0];
    const float* Win   = (const float*)d_in[1];
    const float* Wb    = (const float*)d_in[2];
    const float* Wc    = (const float*)d_in[3];
    const float* Wd    = (const float*)d_in[4];
    const float* Alog  = (const float*)d_in[5];
    const float* Wout  = (const float*)d_in[6];
    const float* bout  = (const float*)d_in[7];
    const float* Wskip = (const float*)d_in[8];
    float* out = (float*)d_out;

    dim3 g1(HIDN / BN, TT / BM);          // (64, 64)
    proj_kernel<<<g1, 256>>>(x, Win, Wb, Wc, Wd, Alog);

    chunk_scan_kernel<<<dim3(NCH, HIDN / 256), 256>>>();
    chunk_combine_kernel<<<HIDN / 256, 256>>>();
    scan_apply_kernel<<<dim3(NCH, HIDN / 256), 256>>>();

    out_kernel<<<TT, 256>>>(x, Wout, bout, Wskip, out);
}

// round 3
// speedup vs baseline: 1.7826x; 1.7826x over previous
#include <cuda_runtime.h>
#include <cuda_bf16.h>
#include <cstdint>

#define TT    8192
#define OBSN  512
#define HIDN  2048
#define NOBJN 8
#define CH    64
#define NCH   128   // TT / CH

// ---------------- scratch (device globals; no allocation allowed) ----------
__device__ float g_Abar[TT * HIDN];
__device__ float g_Bx  [TT * HIDN];
__device__ float g_C   [TT * HIDN];
__device__ float g_y   [TT * HIDN];
__device__ float g_P    [NCH * HIDN];
__device__ float g_E    [NCH * HIDN];
__device__ float g_carry[NCH * HIDN];

// bf16 split copies
__device__ __nv_bfloat16 g_xh[TT * OBSN];
__device__ __nv_bfloat16 g_xl[TT * OBSN];
__device__ __nv_bfloat16 g_wh[4 * HIDN * OBSN];
__device__ __nv_bfloat16 g_wl[4 * HIDN * OBSN];

// ---------------- helpers ---------------------------------------------------
__device__ __forceinline__ uint32_t smem_u32(const void* p) {
    uint32_t a;
    asm("{ .reg .u64 t; cvta.to.shared.u64 t, %1; cvt.u32.u64 %0, t; }"
        : "=r"(a) : "l"(p));
    return a;
}

__device__ __forceinline__ void cp16(uint32_t dst, const void* src) {
    asm volatile("cp.async.cg.shared.global [%0], [%1], 16;"
                 :: "r"(dst), "l"(src) : "memory");
}
#define CP_COMMIT() asm volatile("cp.async.commit_group;" ::: "memory")
#define CP_WAIT(n)  asm volatile("cp.async.wait_group %0;" :: "n"(n) : "memory")

__device__ __forceinline__ void ldm_x4(uint32_t* r, uint32_t addr) {
    asm volatile("ldmatrix.sync.aligned.m8n8.x4.shared.b16 {%0,%1,%2,%3}, [%4];"
                 : "=r"(r[0]), "=r"(r[1]), "=r"(r[2]), "=r"(r[3]) : "r"(addr));
}

__device__ __forceinline__ void mma_bf16(float* c, const uint32_t* a,
                                         const uint32_t* b) {
    asm volatile(
        "mma.sync.aligned.m16n8k16.row.col.f32.bf16.bf16.f32 "
        "{%0,%1,%2,%3}, {%4,%5,%6,%7}, {%8,%9}, {%0,%1,%2,%3};"
        : "+f"(c[0]), "+f"(c[1]), "+f"(c[2]), "+f"(c[3])
        : "r"(a[0]), "r"(a[1]), "r"(a[2]), "r"(a[3]), "r"(b[0]), "r"(b[1]));
}

// swizzled byte offset within a [rows][32 bf16] tile (64B rows)
__device__ __forceinline__ uint32_t swz(int row, int c16) {
    return (uint32_t)(row * 64 + ((c16 ^ (row & 3)) << 4));
}

// ---------------- K0: fp32 -> (bf16 hi, bf16 lo) split ----------------------
__global__ __launch_bounds__(256)
void split_kernel(const float* __restrict__ src,
                  __nv_bfloat16* __restrict__ hi,
                  __nv_bfloat16* __restrict__ lo, int n4)
{
    int i = blockIdx.x * 256 + threadIdx.x;
    if (i >= n4) return;
    float4 v = ((const float4*)src)[i];
    __nv_bfloat16 h0 = __float2bfloat16(v.x);
    __nv_bfloat16 h1 = __float2bfloat16(v.y);
    __nv_bfloat16 h2 = __float2bfloat16(v.z);
    __nv_bfloat16 h3 = __float2bfloat16(v.w);
    __nv_bfloat16 l0 = __float2bfloat16(v.x - __bfloat162float(h0));
    __nv_bfloat16 l1 = __float2bfloat16(v.y - __bfloat162float(h1));
    __nv_bfloat16 l2 = __float2bfloat16(v.z - __bfloat162float(h2));
    __nv_bfloat16 l3 = __float2bfloat16(v.w - __bfloat162float(h3));
    __nv_bfloat162* hp = (__nv_bfloat162*)hi;
    __nv_bfloat162* lp = (__nv_bfloat162*)lo;
    hp[i * 2 + 0] = __nv_bfloat162(h0, h1);
    hp[i * 2 + 1] = __nv_bfloat162(h2, h3);
    lp[i * 2 + 0] = __nv_bfloat162(l0, l1);
    lp[i * 2 + 1] = __nv_bfloat162(l2, l3);
}

// ---------------- K1: fused 4-projection GEMM via mma.sync bf16x3 ----------
// CTA tile: M=128 (t), N=64 (h), 4 matrices. Warp w: matrix (w&3),
// M-half (w>>2), warp tile 64x64. K chunks of 32, double-buffered cp.async.
#define PM 128
#define PN 64
#define KC 32
#define NKC (OBSN / KC)           // 16
#define X_TILE_B   8192           // 128*32*2
#define W_TILE_B   4096           // 64*32*2
#define STAGE_B    49152          // 2*X + 8*W
#define PROJ_SMEM  (2 * STAGE_B)  // 96KB

__global__ __launch_bounds__(256, 1)
void proj_mma_kernel(const float* __restrict__ Alog)
{
    extern __shared__ char smem[];
    const uint32_t sbase = smem_u32(smem);
    const int tid  = threadIdx.x;
    const int wid  = tid >> 5;
    const int lane = tid & 31;
    const int t0   = blockIdx.y * PM;
    const int h0   = blockIdx.x * PN;
    const int m    = wid & 3;       // matrix index
    const int mh   = wid >> 2;      // M-half (0: rows 0-63, 1: rows 64-127)

    float acc[4][8][4];
#pragma unroll
    for (int i = 0; i < 4; i++)
#pragma unroll
        for (int j = 0; j < 8; j++)
#pragma unroll
            for (int k = 0; k < 4; k++) acc[i][j][k] = 0.f;

    // ---- cp.async stage loader ----
    auto issue = [&](int s) {
        const int buf = s & 1;
        const uint32_t sb = sbase + buf * STAGE_B;
        const int kc8 = s * (KC / 8);     // chunk offset in 8-elem units
        // x hi/lo tiles: 512 16B-chunks each -> 2 per thread per tile
#pragma unroll
        for (int j = 0; j < 2; j++) {
            int id = tid + j * 256;
            int row = id >> 2, c16 = id & 3;
            const __nv_bfloat16* s0 = g_xh + (size_t)(t0 + row) * OBSN + (kc8 + c16) * 8;
            const __nv_bfloat16* s1 = g_xl + (size_t)(t0 + row) * OBSN + (kc8 + c16) * 8;
            cp16(sb + swz(row, c16), s0);
            cp16(sb + X_TILE_B + swz(row, c16), s1);
        }
        // W hi/lo tiles: 4 mats x 256 chunks -> 1 per thread per (mat,half)
        {
            int row = tid >> 2, c16 = tid & 3;
#pragma unroll
            for (int mm = 0; mm < 4; mm++) {
                size_t gsrc = ((size_t)mm * HIDN + h0 + row) * OBSN + (size_t)(kc8 + c16) * 8;
                cp16(sb + 2 * X_TILE_B + mm * W_TILE_B + swz(row, c16), g_wh + gsrc);
                cp16(sb + 2 * X_TILE_B + (4 + mm) * W_TILE_B + swz(row, c16), g_wl + gsrc);
            }
        }
        CP_COMMIT();
    };

    issue(0);

    for (int s = 0; s < NKC; s++) {
        if (s + 1 < NKC) { issue(s + 1); CP_WAIT(1); }
        else             { CP_WAIT(0); }
        __syncthreads();

        const uint32_t sb = sbase + (s & 1) * STAGE_B;
        const uint32_t wbase_h = sb + 2 * X_TILE_B + m * W_TILE_B;
        const uint32_t wbase_l = wbase_h + 4 * W_TILE_B;

#pragma unroll
        for (int ks = 0; ks < 2; ks++) {          // two k16 steps per chunk
#pragma unroll
            for (int combo = 0; combo < 3; combo++) {
                // combo 0: xh*wh, 1: xh*wl, 2: xl*wh
                const uint32_t abase = sb + (combo == 2 ? X_TILE_B : 0);
                const uint32_t bbase = (combo == 1) ? wbase_l : wbase_h;

                uint32_t a[4][4];
#pragma unroll
                for (int mi = 0; mi < 4; mi++) {
                    int row = mh * 64 + mi * 16 + (lane & 15);
                    int c16 = ks * 2 + (lane >> 4);
                    ldm_x4(a[mi], abase + swz(row, c16));
                }
                uint32_t b[8][2];
#pragma unroll
                for (int np = 0; np < 4; np++) {
                    int row = np * 16 + (lane & 7) + ((lane >> 4) << 3);
                    int c16 = ks * 2 + ((lane >> 3) & 1);
                    uint32_t r[4];
                    ldm_x4(r, bbase + swz(row, c16));
                    b[2 * np][0] = r[0]; b[2 * np][1] = r[1];
                    b[2 * np + 1][0] = r[2]; b[2 * np + 1][1] = r[3];
                }
#pragma unroll
                for (int mi = 0; mi < 4; mi++)
#pragma unroll
                    for (int nj = 0; nj < 8; nj++)
                        mma_bf16(acc[mi][nj], a[mi], b[nj]);
            }
        }
        __syncthreads();
    }

    // ---- epilogue: exchange x_state, compute A_bar / Bx / C ----
    // smem reused as float [128][68]
    float* sf = (float*)smem;
    const int ES = 68;
    const int rbase = mh * 64 + (lane >> 2);
    const int cbase = 2 * (lane & 3);

    if (m == 0) {   // x_state -> smem
#pragma unroll
        for (int mi = 0; mi < 4; mi++)
#pragma unroll
            for (int nj = 0; nj < 8; nj++) {
                int r = rbase + mi * 16, c = nj * 8 + cbase;
                sf[(r)     * ES + c]     = acc[mi][nj][0];
                sf[(r)     * ES + c + 1] = acc[mi][nj][1];
                sf[(r + 8) * ES + c]     = acc[mi][nj][2];
                sf[(r + 8) * ES + c + 1] = acc[mi][nj][3];
            }
    }
    if (m == 2) {   // C direct
#pragma unroll
        for (int mi = 0; mi < 4; mi++)
#pragma unroll
            for (int nj = 0; nj < 8; nj++) {
                int r = rbase + mi * 16, c = nj * 8 + cbase;
                size_t i0 = (size_t)(t0 + r) * HIDN + h0 + c;
                size_t i1 = (size_t)(t0 + r + 8) * HIDN + h0 + c;
                *(float2*)&g_C[i0] = make_float2(acc[mi][nj][0], acc[mi][nj][1]);
                *(float2*)&g_C[i1] = make_float2(acc[mi][nj][2], acc[mi][nj][3]);
            }
    }
    if (m == 3) {   // delta -> A_bar
#pragma unroll
        for (int mi = 0; mi < 4; mi++)
#pragma unroll
            for (int nj = 0; nj < 8; nj++) {
                int r = rbase + mi * 16, c = nj * 8 + cbase;
                float aA0 = -expf(__ldg(&Alog[h0 + c]));
                float aA1 = -expf(__ldg(&Alog[h0 + c + 1]));
                float d0 = 1.f / (1.f + expf(-acc[mi][nj][0]));
                float d1 = 1.f / (1.f + expf(-acc[mi][nj][1]));
                float d2 = 1.f / (1.f + expf(-acc[mi][nj][2]));
                float d3 = 1.f / (1.f + expf(-acc[mi][nj][3]));
                size_t i0 = (size_t)(t0 + r) * HIDN + h0 + c;
                size_t i1 = (size_t)(t0 + r + 8) * HIDN + h0 + c;
                *(float2*)&g_Abar[i0] = make_float2(expf(d0 * aA0), expf(d1 * aA1));
                *(float2*)&g_Abar[i1] = make_float2(expf(d2 * aA0), expf(d3 * aA1));
            }
    }
    __syncthreads();
    if (m == 1) {   // B * x_state
#pragma unroll
        for (int mi = 0; mi < 4; mi++)
#pragma unroll
            for (int nj = 0; nj < 8; nj++) {
                int r = rbase + mi * 16, c = nj * 8 + cbase;
                float x0 = sf[(r)     * ES + c];
                float x1 = sf[(r)     * ES + c + 1];
                float x2 = sf[(r + 8) * ES + c];
                float x3 = sf[(r + 8) * ES + c + 1];
                size_t i0 = (size_t)(t0 + r) * HIDN + h0 + c;
                size_t i1 = (size_t)(t0 + r + 8) * HIDN + h0 + c;
                *(float2*)&g_Bx[i0] = make_float2(acc[mi][nj][0] * x0, acc[mi][nj][1] * x1);
                *(float2*)&g_Bx[i1] = make_float2(acc[mi][nj][2] * x2, acc[mi][nj][3] * x3);
            }
    }
}

// ---------------- K2: per-chunk scan with zero init -> (P, E) --------------
__global__ __launch_bounds__(256)
void chunk_scan_kernel()
{
    int h = blockIdx.y * 256 + threadIdx.x;
    int c = blockIdx.x;
    float P = 1.f, E = 0.f;
    size_t base = (size_t)c * CH * HIDN + h;
#pragma unroll 4
    for (int i = 0; i < CH; i++) {
        float a  = g_Abar[base + (size_t)i * HIDN];
        float bx = g_Bx  [base + (size_t)i * HIDN];
        E = a * E + bx;
        P *= a;
    }
    g_P[(size_t)c * HIDN + h] = P;
    g_E[(size_t)c * HIDN + h] = E;
}

// ---------------- K3: serial chunk combine -> per-chunk carry-in -----------
__global__ __launch_bounds__(256)
void chunk_combine_kernel()
{
    int h = blockIdx.x * 256 + threadIdx.x;
    float H = 0.f;
    for (int c = 0; c < NCH; c++) {
        g_carry[(size_t)c * HIDN + h] = H;
        H = g_P[(size_t)c * HIDN + h] * H + g_E[(size_t)c * HIDN + h];
    }
}

// ---------------- K4: re-scan with carry, y = C * h ------------------------
__global__ __launch_bounds__(256)
void scan_apply_kernel()
{
    int h = blockIdx.y * 256 + threadIdx.x;
    int c = blockIdx.x;
    float H = g_carry[(size_t)c * HIDN + h];
    size_t base = (size_t)c * CH * HIDN + h;
#pragma unroll 4
    for (int i = 0; i < CH; i++) {
        size_t idx = base + (size_t)i * HIDN;
        float a = g_Abar[idx];
        H = a * H + g_Bx[idx];
        g_y[idx] = g_C[idx] * H;
    }
}

// ---------------- K5: out = y @ W_out^T + b_out + x @ W_skip^T -------------
__global__ __launch_bounds__(256)
void out_kernel(const float* __restrict__ x,
                const float* __restrict__ Wout,
                const float* __restrict__ bout,
                const float* __restrict__ Wskip,
                float* __restrict__ out)
{
    int t  = blockIdx.x;
    int tx = threadIdx.x;
    float p[NOBJN];
#pragma unroll
    for (int j = 0; j < NOBJN; j++) p[j] = 0.f;

    for (int h = tx; h < HIDN; h += 256) {
        float yv = g_y[(size_t)t * HIDN + h];
#pragma unroll
        for (int j = 0; j < NOBJN; j++)
            p[j] += yv * Wout[(size_t)j * HIDN + h];
    }
    for (int k = tx; k < OBSN; k += 256) {
        float xv = x[(size_t)t * OBSN + k];
#pragma unroll
        for (int j = 0; j < NOBJN; j++)
            p[j] += xv * Wskip[(size_t)j * OBSN + k];
    }

#pragma unroll
    for (int off = 16; off > 0; off >>= 1)
#pragma unroll
        for (int j = 0; j < NOBJN; j++)
            p[j] += __shfl_xor_sync(0xffffffffu, p[j], off);

    __shared__ float s[NOBJN];
    if (tx < NOBJN) s[tx] = 0.f;
    __syncthreads();
    if ((tx & 31) == 0) {
#pragma unroll
        for (int j = 0; j < NOBJN; j++)
            atomicAdd(&s[j], p[j]);
    }
    __syncthreads();
    if (tx < NOBJN)
        out[(size_t)t * NOBJN + tx] = s[tx] + bout[tx];
}

// ---------------- launch ---------------------------------------------------
extern "C" void kernel_launch(void* const* d_in, const int* in_sizes, int n_in,
                              void* d_out, int out_size)
{
    const float* x     = (const float*)d_in[0];
    const float* Win   = (const float*)d_in[1];
    const float* Wb    = (const float*)d_in[2];
    const float* Wc    = (const float*)d_in[3];
    const float* Wd    = (const float*)d_in[4];
    const float* Alog  = (const float*)d_in[5];
    const float* Wout  = (const float*)d_in[6];
    const float* bout  = (const float*)d_in[7];
    const float* Wskip = (const float*)d_in[8];
    float* out = (float*)d_out;

    // resolve device-global scratch addresses
    __nv_bfloat16 *xh, *xl, *wh, *wl;
    cudaGetSymbolAddress((void**)&xh, g_xh);
    cudaGetSymbolAddress((void**)&xl, g_xl);
    cudaGetSymbolAddress((void**)&wh, g_wh);
    cudaGetSymbolAddress((void**)&wl, g_wl);

    // split x and the 4 weight matrices into bf16 hi/lo
    {
        int n4 = TT * OBSN / 4;
        split_kernel<<<(n4 + 255) / 256, 256>>>(x, xh, xl, n4);
        int w4 = HIDN * OBSN / 4;
        const float* Ws[4] = {Win, Wb, Wc, Wd};
        for (int mm = 0; mm < 4; mm++)
            split_kernel<<<(w4 + 255) / 256, 256>>>(
                Ws[mm], wh + (size_t)mm * HIDN * OBSN,
                wl + (size_t)mm * HIDN * OBSN, w4);
    }

    cudaFuncSetAttribute(proj_mma_kernel,
                         cudaFuncAttributeMaxDynamicSharedMemorySize, PROJ_SMEM);
    dim3 g1(HIDN / PN, TT / PM);            // (32, 64)
    proj_mma_kernel<<<g1, 256, PROJ_SMEM>>>(Alog);

    chunk_scan_kernel<<<dim3(NCH, HIDN / 256), 256>>>();
    chunk_combine_kernel<<<HIDN / 256, 256>>>();
    scan_apply_kernel<<<dim3(NCH, HIDN / 256), 256>>>();

    out_kernel<<<TT, 256>>>(x, Wout, bout, Wskip, out);
}

// round 4
// speedup vs baseline: 2.2392x; 1.2561x over previous
#include <cuda_runtime.h>
#include <cuda_bf16.h>
#include <cstdint>

#define TT    8192
#define OBSN  512
#define HIDN  2048
#define NOBJN 8
#define CH    64
#define NCH   128   // TT / CH

// ---------------- scratch (device globals; no allocation allowed) ----------
__device__ float g_Abar[TT * HIDN];
__device__ float g_Bx  [TT * HIDN];
__device__ float g_C   [TT * HIDN];
__device__ float g_y   [TT * HIDN];
__device__ float g_P    [NCH * HIDN];
__device__ float g_E    [NCH * HIDN];
__device__ float g_carry[NCH * HIDN];

// bf16 split copies
__device__ __nv_bfloat16 g_xh[TT * OBSN];
__device__ __nv_bfloat16 g_xl[TT * OBSN];
__device__ __nv_bfloat16 g_wh[4 * HIDN * OBSN];
__device__ __nv_bfloat16 g_wl[4 * HIDN * OBSN];

// ---------------- helpers ---------------------------------------------------
__device__ __forceinline__ uint32_t smem_u32(const void* p) {
    uint32_t a;
    asm("{ .reg .u64 t; cvta.to.shared.u64 t, %1; cvt.u32.u64 %0, t; }"
        : "=r"(a) : "l"(p));
    return a;
}

__device__ __forceinline__ void cp16(uint32_t dst, const void* src) {
    asm volatile("cp.async.cg.shared.global [%0], [%1], 16;"
                 :: "r"(dst), "l"(src) : "memory");
}
#define CP_COMMIT() asm volatile("cp.async.commit_group;" ::: "memory")
#define CP_WAIT(n)  asm volatile("cp.async.wait_group %0;" :: "n"(n) : "memory")

__device__ __forceinline__ void ldm_x4(uint32_t* r, uint32_t addr) {
    asm volatile("ldmatrix.sync.aligned.m8n8.x4.shared.b16 {%0,%1,%2,%3}, [%4];"
                 : "=r"(r[0]), "=r"(r[1]), "=r"(r[2]), "=r"(r[3]) : "r"(addr));
}

__device__ __forceinline__ void mma_bf16(float* c, const uint32_t* a,
                                         const uint32_t* b) {
    asm volatile(
        "mma.sync.aligned.m16n8k16.row.col.f32.bf16.bf16.f32 "
        "{%0,%1,%2,%3}, {%4,%5,%6,%7}, {%8,%9}, {%0,%1,%2,%3};"
        : "+f"(c[0]), "+f"(c[1]), "+f"(c[2]), "+f"(c[3])
        : "r"(a[0]), "r"(a[1]), "r"(a[2]), "r"(a[3]), "r"(b[0]), "r"(b[1]));
}

// conflict-free swizzle: rows are 64B; map 8 consecutive rows to 8 distinct
// 16B slots mod 128B:  slot = (row parity)*64 + (c16 ^ ((row>>1)&3))*16
__device__ __forceinline__ uint32_t swz(int row, int c16) {
    return (uint32_t)(row * 64 + (((c16 ^ (row >> 1)) & 3) << 4));
}

// ---------------- K0: fp32 -> (bf16 hi, bf16 lo) split ----------------------
__global__ __launch_bounds__(256)
void split_kernel(const float* __restrict__ src,
                  __nv_bfloat16* __restrict__ hi,
                  __nv_bfloat16* __restrict__ lo, int n4)
{
    int i = blockIdx.x * 256 + threadIdx.x;
    if (i >= n4) return;
    float4 v = ((const float4*)src)[i];
    __nv_bfloat16 h0 = __float2bfloat16(v.x);
    __nv_bfloat16 h1 = __float2bfloat16(v.y);
    __nv_bfloat16 h2 = __float2bfloat16(v.z);
    __nv_bfloat16 h3 = __float2bfloat16(v.w);
    __nv_bfloat16 l0 = __float2bfloat16(v.x - __bfloat162float(h0));
    __nv_bfloat16 l1 = __float2bfloat16(v.y - __bfloat162float(h1));
    __nv_bfloat16 l2 = __float2bfloat16(v.z - __bfloat162float(h2));
    __nv_bfloat16 l3 = __float2bfloat16(v.w - __bfloat162float(h3));
    __nv_bfloat162* hp = (__nv_bfloat162*)hi;
    __nv_bfloat162* lp = (__nv_bfloat162*)lo;
    hp[i * 2 + 0] = __nv_bfloat162(h0, h1);
    hp[i * 2 + 1] = __nv_bfloat162(h2, h3);
    lp[i * 2 + 0] = __nv_bfloat162(l0, l1);
    lp[i * 2 + 1] = __nv_bfloat162(l2, l3);
}

__global__ __launch_bounds__(256)
void splitw_kernel(const float* __restrict__ w0, const float* __restrict__ w1,
                   const float* __restrict__ w2, const float* __restrict__ w3)
{
    const float* src[4] = {w0, w1, w2, w3};
    int mm = blockIdx.y;
    int n4 = HIDN * OBSN / 4;
    int i = blockIdx.x * 256 + threadIdx.x;
    if (i >= n4) return;
    float4 v = ((const float4*)src[mm])[i];
    size_t off = (size_t)mm * (HIDN * OBSN / 2);
    __nv_bfloat162* hp = (__nv_bfloat162*)g_wh + off;
    __nv_bfloat162* lp = (__nv_bfloat162*)g_wl + off;
    __nv_bfloat16 h0 = __float2bfloat16(v.x);
    __nv_bfloat16 h1 = __float2bfloat16(v.y);
    __nv_bfloat16 h2 = __float2bfloat16(v.z);
    __nv_bfloat16 h3 = __float2bfloat16(v.w);
    hp[i * 2 + 0] = __nv_bfloat162(h0, h1);
    hp[i * 2 + 1] = __nv_bfloat162(h2, h3);
    lp[i * 2 + 0] = __nv_bfloat162(__float2bfloat16(v.x - __bfloat162float(h0)),
                                   __float2bfloat16(v.y - __bfloat162float(h1)));
    lp[i * 2 + 1] = __nv_bfloat162(__float2bfloat16(v.z - __bfloat162float(h2)),
                                   __float2bfloat16(v.w - __bfloat162float(h3)));
}

// ---------------- K1: fused 4-projection GEMM via mma.sync bf16x3 ----------
// CTA tile: M=128 (t), N=32 (h), 4 matrices. Warp w: matrix (w&3),
// M-half (w>>2), warp tile 64x32. K chunks of 32, 3-stage cp.async.
#define PM 128
#define PN 32
#define KC 32
#define NKC (OBSN / KC)           // 16
#define X_TILE_B   8192           // 128*32*2
#define W_TILE_B   2048           // 32*32*2
#define STAGE_B    32768          // 2*X + 8*W
#define NSTAGE 3
#define PROJ_SMEM  (NSTAGE * STAGE_B)  // 96KB

__global__ __launch_bounds__(256, 2)
void proj_mma_kernel(const float* __restrict__ Alog)
{
    extern __shared__ char smem[];
    const uint32_t sbase = smem_u32(smem);
    const int tid  = threadIdx.x;
    const int wid  = tid >> 5;
    const int lane = tid & 31;
    const int t0   = blockIdx.y * PM;
    const int h0   = blockIdx.x * PN;
    const int m    = wid & 3;       // matrix index
    const int mh   = wid >> 2;      // M-half (0: rows 0-63, 1: rows 64-127)

    float acc[4][4][4];
#pragma unroll
    for (int i = 0; i < 4; i++)
#pragma unroll
        for (int j = 0; j < 4; j++)
#pragma unroll
            for (int k = 0; k < 4; k++) acc[i][j][k] = 0.f;

    // ---- cp.async stage loader: 8 cp16 per thread ----
    auto issue = [&](int s) {
        if (s >= NKC) { CP_COMMIT(); return; }
        const uint32_t sb = sbase + (uint32_t)(s % NSTAGE) * STAGE_B;
        const int kel = s * KC;                 // k offset in elements
        // x hi/lo: 512 chunks each (128 rows x 4 c16) -> 2 per thread per tile
#pragma unroll
        for (int j = 0; j < 2; j++) {
            int id  = tid + j * 256;
            int row = id >> 2, c16 = id & 3;
            size_t gs = (size_t)(t0 + row) * OBSN + kel + c16 * 8;
            cp16(sb + swz(row, c16), g_xh + gs);
            cp16(sb + X_TILE_B + swz(row, c16), g_xl + gs);
        }
        // W: variant = tid>>7, 128 chunks per (mat,variant) -> 1/thread/mat
        {
            int var = tid >> 7;           // 0=hi, 1=lo
            int id  = tid & 127;
            int row = id >> 2, c16 = id & 3;
            const __nv_bfloat16* base = var ? g_wl : g_wh;
            uint32_t dstv = sb + 2 * X_TILE_B + var * 4 * W_TILE_B;
#pragma unroll
            for (int mm = 0; mm < 4; mm++) {
                size_t gs = ((size_t)mm * HIDN + h0 + row) * OBSN + kel + c16 * 8;
                cp16(dstv + mm * W_TILE_B + swz(row, c16), base + gs);
            }
        }
        CP_COMMIT();
    };

    issue(0);
    issue(1);

    for (int s = 0; s < NKC; s++) {
        issue(s + 2);
        CP_WAIT(2);
        __syncthreads();

        const uint32_t sb   = sbase + (uint32_t)(s % NSTAGE) * STAGE_B;
        const uint32_t xh_b = sb;
        const uint32_t xl_b = sb + X_TILE_B;
        const uint32_t wh_b = sb + 2 * X_TILE_B + m * W_TILE_B;
        const uint32_t wl_b = wh_b + 4 * W_TILE_B;

#pragma unroll
        for (int ks = 0; ks < 2; ks++) {
            uint32_t ah[4][4], al[4][4], bh[4][2], bl[4][2];
#pragma unroll
            for (int mi = 0; mi < 4; mi++) {
                int row = mh * 64 + mi * 16 + (lane & 15);
                int c16 = ks * 2 + (lane >> 4);
                ldm_x4(ah[mi], xh_b + swz(row, c16));
                ldm_x4(al[mi], xl_b + swz(row, c16));
            }
#pragma unroll
            for (int np = 0; np < 2; np++) {
                int row = np * 16 + (lane & 7) + ((lane >> 4) << 3);
                int c16 = ks * 2 + ((lane >> 3) & 1);
                uint32_t r[4];
                ldm_x4(r, wh_b + swz(row, c16));
                bh[2 * np][0] = r[0]; bh[2 * np][1] = r[1];
                bh[2 * np + 1][0] = r[2]; bh[2 * np + 1][1] = r[3];
                ldm_x4(r, wl_b + swz(row, c16));
                bl[2 * np][0] = r[0]; bl[2 * np][1] = r[1];
                bl[2 * np + 1][0] = r[2]; bl[2 * np + 1][1] = r[3];
            }
#pragma unroll
            for (int mi = 0; mi < 4; mi++)
#pragma unroll
                for (int nj = 0; nj < 4; nj++) {
                    mma_bf16(acc[mi][nj], ah[mi], bh[nj]);
                    mma_bf16(acc[mi][nj], ah[mi], bl[nj]);
                    mma_bf16(acc[mi][nj], al[mi], bh[nj]);
                }
        }
        __syncthreads();
    }

    // ---- epilogue: exchange x_state, compute A_bar / Bx / C ----
    float* sf = (float*)smem;
    const int ES = 36;
    const int rbase = mh * 64 + (lane >> 2);
    const int cbase = 2 * (lane & 3);

    if (m == 0) {   // x_state -> smem
#pragma unroll
        for (int mi = 0; mi < 4; mi++)
#pragma unroll
            for (int nj = 0; nj < 4; nj++) {
                int r = rbase + mi * 16, c = nj * 8 + cbase;
                sf[(r)     * ES + c]     = acc[mi][nj][0];
                sf[(r)     * ES + c + 1] = acc[mi][nj][1];
                sf[(r + 8) * ES + c]     = acc[mi][nj][2];
                sf[(r + 8) * ES + c + 1] = acc[mi][nj][3];
            }
    }
    if (m == 2) {   // C direct
#pragma unroll
        for (int mi = 0; mi < 4; mi++)
#pragma unroll
            for (int nj = 0; nj < 4; nj++) {
                int r = rbase + mi * 16, c = nj * 8 + cbase;
                size_t i0 = (size_t)(t0 + r) * HIDN + h0 + c;
                size_t i1 = (size_t)(t0 + r + 8) * HIDN + h0 + c;
                *(float2*)&g_C[i0] = make_float2(acc[mi][nj][0], acc[mi][nj][1]);
                *(float2*)&g_C[i1] = make_float2(acc[mi][nj][2], acc[mi][nj][3]);
            }
    }
    if (m == 3) {   // delta -> A_bar
#pragma unroll
        for (int mi = 0; mi < 4; mi++)
#pragma unroll
            for (int nj = 0; nj < 4; nj++) {
                int r = rbase + mi * 16, c = nj * 8 + cbase;
                float aA0 = -expf(__ldg(&Alog[h0 + c]));
                float aA1 = -expf(__ldg(&Alog[h0 + c + 1]));
                float d0 = 1.f / (1.f + expf(-acc[mi][nj][0]));
                float d1 = 1.f / (1.f + expf(-acc[mi][nj][1]));
                float d2 = 1.f / (1.f + expf(-acc[mi][nj][2]));
                float d3 = 1.f / (1.f + expf(-acc[mi][nj][3]));
                size_t i0 = (size_t)(t0 + r) * HIDN + h0 + c;
                size_t i1 = (size_t)(t0 + r + 8) * HIDN + h0 + c;
                *(float2*)&g_Abar[i0] = make_float2(expf(d0 * aA0), expf(d1 * aA1));
                *(float2*)&g_Abar[i1] = make_float2(expf(d2 * aA0), expf(d3 * aA1));
            }
    }
    __syncthreads();
    if (m == 1) {   // B * x_state
#pragma unroll
        for (int mi = 0; mi < 4; mi++)
#pragma unroll
            for (int nj = 0; nj < 4; nj++) {
                int r = rbase + mi * 16, c = nj * 8 + cbase;
                float x0 = sf[(r)     * ES + c];
                float x1 = sf[(r)     * ES + c + 1];
                float x2 = sf[(r + 8) * ES + c];
                float x3 = sf[(r + 8) * ES + c + 1];
                size_t i0 = (size_t)(t0 + r) * HIDN + h0 + c;
                size_t i1 = (size_t)(t0 + r + 8) * HIDN + h0 + c;
                *(float2*)&g_Bx[i0] = make_float2(acc[mi][nj][0] * x0, acc[mi][nj][1] * x1);
                *(float2*)&g_Bx[i1] = make_float2(acc[mi][nj][2] * x2, acc[mi][nj][3] * x3);
            }
    }
}

// ---------------- K2: per-chunk scan with zero init -> (P, E) --------------
__global__ __launch_bounds__(256)
void chunk_scan_kernel()
{
    int h = blockIdx.y * 256 + threadIdx.x;
    int c = blockIdx.x;
    float P = 1.f, E = 0.f;
    size_t base = (size_t)c * CH * HIDN + h;
#pragma unroll 4
    for (int i = 0; i < CH; i++) {
        float a  = g_Abar[base + (size_t)i * HIDN];
        float bx = g_Bx  [base + (size_t)i * HIDN];
        E = a * E + bx;
        P *= a;
    }
    g_P[(size_t)c * HIDN + h] = P;
    g_E[(size_t)c * HIDN + h] = E;
}

// ---------------- K3: serial chunk combine -> per-chunk carry-in -----------
__global__ __launch_bounds__(256)
void chunk_combine_kernel()
{
    int h = blockIdx.x * 256 + threadIdx.x;
    float H = 0.f;
    for (int c = 0; c < NCH; c++) {
        g_carry[(size_t)c * HIDN + h] = H;
        H = g_P[(size_t)c * HIDN + h] * H + g_E[(size_t)c * HIDN + h];
    }
}

// ---------------- K4: re-scan with carry, y = C * h ------------------------
__global__ __launch_bounds__(256)
void scan_apply_kernel()
{
    int h = blockIdx.y * 256 + threadIdx.x;
    int c = blockIdx.x;
    float H = g_carry[(size_t)c * HIDN + h];
    size_t base = (size_t)c * CH * HIDN + h;
#pragma unroll 4
    for (int i = 0; i < CH; i++) {
        size_t idx = base + (size_t)i * HIDN;
        float a = g_Abar[idx];
        H = a * H + g_Bx[idx];
        g_y[idx] = g_C[idx] * H;
    }
}

// ---------------- K5: out = y @ W_out^T + b_out + x @ W_skip^T -------------
__global__ __launch_bounds__(256)
void out_kernel(const float* __restrict__ x,
                const float* __restrict__ Wout,
                const float* __restrict__ bout,
                const float* __restrict__ Wskip,
                float* __restrict__ out)
{
    int t  = blockIdx.x;
    int tx = threadIdx.x;
    float p[NOBJN];
#pragma unroll
    for (int j = 0; j < NOBJN; j++) p[j] = 0.f;

    for (int h = tx; h < HIDN; h += 256) {
        float yv = g_y[(size_t)t * HIDN + h];
#pragma unroll
        for (int j = 0; j < NOBJN; j++)
            p[j] += yv * Wout[(size_t)j * HIDN + h];
    }
    for (int k = tx; k < OBSN; k += 256) {
        float xv = x[(size_t)t * OBSN + k];
#pragma unroll
        for (int j = 0; j < NOBJN; j++)
            p[j] += xv * Wskip[(size_t)j * OBSN + k];
    }

#pragma unroll
    for (int off = 16; off > 0; off >>= 1)
#pragma unroll
        for (int j = 0; j < NOBJN; j++)
            p[j] += __shfl_xor_sync(0xffffffffu, p[j], off);

    __shared__ float s[NOBJN];
    if (tx < NOBJN) s[tx] = 0.f;
    __syncthreads();
    if ((tx & 31) == 0) {
#pragma unroll
        for (int j = 0; j < NOBJN; j++)
            atomicAdd(&s[j], p[j]);
    }
    __syncthreads();
    if (tx < NOBJN)
        out[(size_t)t * NOBJN + tx] = s[tx] + bout[tx];
}

// ---------------- launch ---------------------------------------------------
extern "C" void kernel_launch(void* const* d_in, const int* in_sizes, int n_in,
                              void* d_out, int out_size)
{
    const float* x     = (const float*)d_in[0];
    const float* Win   = (const float*)d_in[1];
    const float* Wb    = (const float*)d_in[2];
    const float* Wc    = (const float*)d_in[3];
    const float* Wd    = (const float*)d_in[4];
    const float* Alog  = (const float*)d_in[5];
    const float* Wout  = (const float*)d_in[6];
    const float* bout  = (const float*)d_in[7];
    const float* Wskip = (const float*)d_in[8];
    float* out = (float*)d_out;

    __nv_bfloat16 *xh, *xl;
    cudaGetSymbolAddress((void**)&xh, g_xh);
    cudaGetSymbolAddress((void**)&xl, g_xl);

    {
        int n4 = TT * OBSN / 4;
        split_kernel<<<(n4 + 255) / 256, 256>>>(x, xh, xl, n4);
        int w4 = HIDN * OBSN / 4;
        splitw_kernel<<<dim3((w4 + 255) / 256, 4), 256>>>(Win, Wb, Wc, Wd);
    }

    cudaFuncSetAttribute(proj_mma_kernel,
                         cudaFuncAttributeMaxDynamicSharedMemorySize, PROJ_SMEM);
    dim3 g1(HIDN / PN, TT / PM);            // (64, 64)
    proj_mma_kernel<<<g1, 256, PROJ_SMEM>>>(Alog);

    chunk_scan_kernel<<<dim3(NCH, HIDN / 256), 256>>>();
    chunk_combine_kernel<<<HIDN / 256, 256>>>();
    scan_apply_kernel<<<dim3(NCH, HIDN / 256), 256>>>();

    out_kernel<<<TT, 256>>>(x, Wout, bout, Wskip, out);
}

// round 8
// speedup vs baseline: 2.2395x; 1.0001x over previous
#include <cuda_runtime.h>
#include <cuda_bf16.h>
#include <cstdint>

#define TT    8192
#define OBSN  512
#define HIDN  2048
#define NOBJN 8
#define CH    64
#define NCH   128   // TT / CH

// ---------------- scratch (device globals; no allocation allowed) ----------
__device__ float g_Abar[TT * HIDN];
__device__ float g_Bx  [TT * HIDN];
__device__ float g_C   [TT * HIDN];
__device__ float g_y   [TT * HIDN];
__device__ float g_P    [NCH * HIDN];
__device__ float g_E    [NCH * HIDN];
__device__ float g_carry[NCH * HIDN];

// bf16 split copies
__device__ __nv_bfloat16 g_xh[TT * OBSN];
__device__ __nv_bfloat16 g_xl[TT * OBSN];
__device__ __nv_bfloat16 g_wh[4 * HIDN * OBSN];
__device__ __nv_bfloat16 g_wl[4 * HIDN * OBSN];

// ---------------- helpers ---------------------------------------------------
__device__ __forceinline__ uint32_t smem_u32(const void* p) {
    uint32_t a;
    asm("{ .reg .u64 t; cvta.to.shared.u64 t, %1; cvt.u32.u64 %0, t; }"
        : "=r"(a) : "l"(p));
    return a;
}

__device__ __forceinline__ void cp16(uint32_t dst, const void* src) {
    asm volatile("cp.async.cg.shared.global [%0], [%1], 16;"
                 :: "r"(dst), "l"(src) : "memory");
}
#define CP_COMMIT() asm volatile("cp.async.commit_group;" ::: "memory")
#define CP_WAIT(n)  asm volatile("cp.async.wait_group %0;" :: "n"(n) : "memory")

__device__ __forceinline__ void ldm_x4(uint32_t* r, uint32_t addr) {
    asm volatile("ldmatrix.sync.aligned.m8n8.x4.shared.b16 {%0,%1,%2,%3}, [%4];"
                 : "=r"(r[0]), "=r"(r[1]), "=r"(r[2]), "=r"(r[3]) : "r"(addr));
}

__device__ __forceinline__ void mma_bf16(float* c, const uint32_t* a,
                                         const uint32_t* b) {
    asm volatile(
        "mma.sync.aligned.m16n8k16.row.col.f32.bf16.bf16.f32 "
        "{%0,%1,%2,%3}, {%4,%5,%6,%7}, {%8,%9}, {%0,%1,%2,%3};"
        : "+f"(c[0]), "+f"(c[1]), "+f"(c[2]), "+f"(c[3])
        : "r"(a[0]), "r"(a[1]), "r"(a[2]), "r"(a[3]), "r"(b[0]), "r"(b[1]));
}

// conflict-free swizzle: rows are 64B; 8 consecutive rows hit 8 distinct
// 16B slots mod 128B
__device__ __forceinline__ uint32_t swz(int row, int c16) {
    return (uint32_t)(row * 64 + (((c16 ^ (row >> 1)) & 3) << 4));
}

// ---------------- K0: fp32 -> (bf16 hi, bf16 lo) split ----------------------
__global__ __launch_bounds__(256)
void split_kernel(const float* __restrict__ src,
                  __nv_bfloat16* __restrict__ hi,
                  __nv_bfloat16* __restrict__ lo, int n4)
{
    int i = blockIdx.x * 256 + threadIdx.x;
    if (i >= n4) return;
    float4 v = ((const float4*)src)[i];
    __nv_bfloat16 h0 = __float2bfloat16(v.x);
    __nv_bfloat16 h1 = __float2bfloat16(v.y);
    __nv_bfloat16 h2 = __float2bfloat16(v.z);
    __nv_bfloat16 h3 = __float2bfloat16(v.w);
    __nv_bfloat162* hp = (__nv_bfloat162*)hi;
    __nv_bfloat162* lp = (__nv_bfloat162*)lo;
    hp[i * 2 + 0] = __nv_bfloat162(h0, h1);
    hp[i * 2 + 1] = __nv_bfloat162(h2, h3);
    lp[i * 2 + 0] = __nv_bfloat162(__float2bfloat16(v.x - __bfloat162float(h0)),
                                   __float2bfloat16(v.y - __bfloat162float(h1)));
    lp[i * 2 + 1] = __nv_bfloat162(__float2bfloat16(v.z - __bfloat162float(h2)),
                                   __float2bfloat16(v.w - __bfloat162float(h3)));
}

__global__ __launch_bounds__(256)
void splitw_kernel(const float* __restrict__ w0, const float* __restrict__ w1,
                   const float* __restrict__ w2, const float* __restrict__ w3)
{
    const float* src[4] = {w0, w1, w2, w3};
    int mm = blockIdx.y;
    int n4 = HIDN * OBSN / 4;
    int i = blockIdx.x * 256 + threadIdx.x;
    if (i >= n4) return;
    float4 v = ((const float4*)src[mm])[i];
    size_t off = (size_t)mm * (HIDN * OBSN / 2);
    __nv_bfloat162* hp = (__nv_bfloat162*)g_wh + off;
    __nv_bfloat162* lp = (__nv_bfloat162*)g_wl + off;
    __nv_bfloat16 h0 = __float2bfloat16(v.x);
    __nv_bfloat16 h1 = __float2bfloat16(v.y);
    __nv_bfloat16 h2 = __float2bfloat16(v.z);
    __nv_bfloat16 h3 = __float2bfloat16(v.w);
    hp[i * 2 + 0] = __nv_bfloat162(h0, h1);
    hp[i * 2 + 1] = __nv_bfloat162(h2, h3);
    lp[i * 2 + 0] = __nv_bfloat162(__float2bfloat16(v.x - __bfloat162float(h0)),
                                   __float2bfloat16(v.y - __bfloat162float(h1)));
    lp[i * 2 + 1] = __nv_bfloat162(__float2bfloat16(v.z - __bfloat162float(h2)),
                                   __float2bfloat16(v.w - __bfloat162float(h3)));
}

// ---------------- K1: fused 4-projection GEMM via mma.sync bf16x3 ----------
#define PM 128
#define PN 32
#define KC 32
#define NKC (OBSN / KC)           // 16
#define X_TILE_B   8192           // 128*32*2
#define W_TILE_B   2048           // 32*32*2
#define STAGE_B    32768          // 2*X + 8*W
#define NSTAGE 3
#define PROJ_SMEM  (NSTAGE * STAGE_B)  // 96KB

__global__ __launch_bounds__(256, 2)
void proj_mma_kernel(const float* __restrict__ Alog)
{
    extern __shared__ char smem[];
    const uint32_t sbase = smem_u32(smem);
    const int tid  = threadIdx.x;
    const int wid  = tid >> 5;
    const int lane = tid & 31;
    const int t0   = blockIdx.y * PM;
    const int h0   = blockIdx.x * PN;
    const int m    = wid & 3;       // matrix index
    const int mh   = wid >> 2;      // M-half

    float acc[4][4][4];
#pragma unroll
    for (int i = 0; i < 4; i++)
#pragma unroll
        for (int j = 0; j < 4; j++)
#pragma unroll
            for (int k = 0; k < 4; k++) acc[i][j][k] = 0.f;

    auto issue = [&](int s) {
        if (s >= NKC) { CP_COMMIT(); return; }
        const uint32_t sb = sbase + (uint32_t)(s % NSTAGE) * STAGE_B;
        const int kel = s * KC;
#pragma unroll
        for (int j = 0; j < 2; j++) {
            int id  = tid + j * 256;
            int row = id >> 2, c16 = id & 3;
            size_t gs = (size_t)(t0 + row) * OBSN + kel + c16 * 8;
            cp16(sb + swz(row, c16), g_xh + gs);
            cp16(sb + X_TILE_B + swz(row, c16), g_xl + gs);
        }
        {
            int var = tid >> 7;           // 0=hi, 1=lo
            int id  = tid & 127;
            int row = id >> 2, c16 = id & 3;
            const __nv_bfloat16* base = var ? g_wl : g_wh;
            uint32_t dstv = sb + 2 * X_TILE_B + var * 4 * W_TILE_B;
#pragma unroll
            for (int mm = 0; mm < 4; mm++) {
                size_t gs = ((size_t)mm * HIDN + h0 + row) * OBSN + kel + c16 * 8;
                cp16(dstv + mm * W_TILE_B + swz(row, c16), base + gs);
            }
        }
        CP_COMMIT();
    };

    issue(0);
    issue(1);

    for (int s = 0; s < NKC; s++) {
        CP_WAIT(1);            // stage s landed (s+1 may still be in flight)
        __syncthreads();       // all warps done with chunk s-1 -> safe overwrite
        issue(s + 2);          // fills stage (s+2)%3 == (s-1)%3

        const uint32_t sb   = sbase + (uint32_t)(s % NSTAGE) * STAGE_B;
        const uint32_t xh_b = sb;
        const uint32_t xl_b = sb + X_TILE_B;
        const uint32_t wh_b = sb + 2 * X_TILE_B + m * W_TILE_B;
        const uint32_t wl_b = wh_b + 4 * W_TILE_B;

#pragma unroll
        for (int ks = 0; ks < 2; ks++) {
            uint32_t ah[4][4], al[4][4], bh[4][2], bl[4][2];
#pragma unroll
            for (int mi = 0; mi < 4; mi++) {
                int row = mh * 64 + mi * 16 + (lane & 15);
                int c16 = ks * 2 + (lane >> 4);
                ldm_x4(ah[mi], xh_b + swz(row, c16));
                ldm_x4(al[mi], xl_b + swz(row, c16));
            }
#pragma unroll
            for (int np = 0; np < 2; np++) {
                int row = np * 16 + (lane & 7) + ((lane >> 4) << 3);
                int c16 = ks * 2 + ((lane >> 3) & 1);
                uint32_t r[4];
                ldm_x4(r, wh_b + swz(row, c16));
                bh[2 * np][0] = r[0]; bh[2 * np][1] = r[1];
                bh[2 * np + 1][0] = r[2]; bh[2 * np + 1][1] = r[3];
                ldm_x4(r, wl_b + swz(row, c16));
                bl[2 * np][0] = r[0]; bl[2 * np][1] = r[1];
                bl[2 * np + 1][0] = r[2]; bl[2 * np + 1][1] = r[3];
            }
#pragma unroll
            for (int mi = 0; mi < 4; mi++)
#pragma unroll
                for (int nj = 0; nj < 4; nj++) {
                    mma_bf16(acc[mi][nj], ah[mi], bh[nj]);
                    mma_bf16(acc[mi][nj], ah[mi], bl[nj]);
                    mma_bf16(acc[mi][nj], al[mi], bh[nj]);
                }
        }
    }
    __syncthreads();   // protect smem reuse by epilogue

    // ---- epilogue: exchange x_state, compute A_bar / Bx / C ----
    float* sf = (float*)smem;
    const int ES = 36;
    const int rbase = mh * 64 + (lane >> 2);
    const int cbase = 2 * (lane & 3);

    if (m == 0) {   // x_state -> smem
#pragma unroll
        for (int mi = 0; mi < 4; mi++)
#pragma unroll
            for (int nj = 0; nj < 4; nj++) {
                int r = rbase + mi * 16, c = nj * 8 + cbase;
                sf[(r)     * ES + c]     = acc[mi][nj][0];
                sf[(r)     * ES + c + 1] = acc[mi][nj][1];
                sf[(r + 8) * ES + c]     = acc[mi][nj][2];
                sf[(r + 8) * ES + c + 1] = acc[mi][nj][3];
            }
    }
    if (m == 2) {   // C direct
#pragma unroll
        for (int mi = 0; mi < 4; mi++)
#pragma unroll
            for (int nj = 0; nj < 4; nj++) {
                int r = rbase + mi * 16, c = nj * 8 + cbase;
                size_t i0 = (size_t)(t0 + r) * HIDN + h0 + c;
                size_t i1 = (size_t)(t0 + r + 8) * HIDN + h0 + c;
                *(float2*)&g_C[i0] = make_float2(acc[mi][nj][0], acc[mi][nj][1]);
                *(float2*)&g_C[i1] = make_float2(acc[mi][nj][2], acc[mi][nj][3]);
            }
    }
    if (m == 3) {   // delta -> A_bar
#pragma unroll
        for (int mi = 0; mi < 4; mi++)
#pragma unroll
            for (int nj = 0; nj < 4; nj++) {
                int r = rbase + mi * 16, c = nj * 8 + cbase;
                float aA0 = -expf(__ldg(&Alog[h0 + c]));
                float aA1 = -expf(__ldg(&Alog[h0 + c + 1]));
                float d0 = 1.f / (1.f + expf(-acc[mi][nj][0]));
                float d1 = 1.f / (1.f + expf(-acc[mi][nj][1]));
                float d2 = 1.f / (1.f + expf(-acc[mi][nj][2]));
                float d3 = 1.f / (1.f + expf(-acc[mi][nj][3]));
                size_t i0 = (size_t)(t0 + r) * HIDN + h0 + c;
                size_t i1 = (size_t)(t0 + r + 8) * HIDN + h0 + c;
                *(float2*)&g_Abar[i0] = make_float2(expf(d0 * aA0), expf(d1 * aA1));
                *(float2*)&g_Abar[i1] = make_float2(expf(d2 * aA0), expf(d3 * aA1));
            }
    }
    __syncthreads();
    if (m == 1) {   // B * x_state
#pragma unroll
        for (int mi = 0; mi < 4; mi++)
#pragma unroll
            for (int nj = 0; nj < 4; nj++) {
                int r = rbase + mi * 16, c = nj * 8 + cbase;
                float x0 = sf[(r)     * ES + c];
                float x1 = sf[(r)     * ES + c + 1];
                float x2 = sf[(r + 8) * ES + c];
                float x3 = sf[(r + 8) * ES + c + 1];
                size_t i0 = (size_t)(t0 + r) * HIDN + h0 + c;
                size_t i1 = (size_t)(t0 + r + 8) * HIDN + h0 + c;
                *(float2*)&g_Bx[i0] = make_float2(acc[mi][nj][0] * x0, acc[mi][nj][1] * x1);
                *(float2*)&g_Bx[i1] = make_float2(acc[mi][nj][2] * x2, acc[mi][nj][3] * x3);
            }
    }
}

// ---------------- K2: per-chunk scan (float4) -> (P, E) --------------------
__global__ __launch_bounds__(128)
void chunk_scan_kernel()
{
    int h4 = blockIdx.y * 128 + threadIdx.x;      // float4 column
    int c  = blockIdx.x;
    const float4* A4 = (const float4*)g_Abar;
    const float4* B4 = (const float4*)g_Bx;
    float4 P = make_float4(1.f, 1.f, 1.f, 1.f);
    float4 E = make_float4(0.f, 0.f, 0.f, 0.f);
    size_t base = (size_t)c * CH * (HIDN / 4) + h4;
#pragma unroll 4
    for (int i = 0; i < CH; i++) {
        float4 a  = A4[base + (size_t)i * (HIDN / 4)];
        float4 bx = B4[base + (size_t)i * (HIDN / 4)];
        E.x = a.x * E.x + bx.x;  E.y = a.y * E.y + bx.y;
        E.z = a.z * E.z + bx.z;  E.w = a.w * E.w + bx.w;
        P.x *= a.x; P.y *= a.y; P.z *= a.z; P.w *= a.w;
    }
    ((float4*)g_P)[(size_t)c * (HIDN / 4) + h4] = P;
    ((float4*)g_E)[(size_t)c * (HIDN / 4) + h4] = E;
}

// ---------------- K3: serial chunk combine (float4) ------------------------
__global__ __launch_bounds__(256)
void chunk_combine_kernel()
{
    int h4 = blockIdx.x * 256 + threadIdx.x;
    float4 H = make_float4(0.f, 0.f, 0.f, 0.f);
    for (int c = 0; c < NCH; c++) {
        size_t i = (size_t)c * (HIDN / 4) + h4;
        ((float4*)g_carry)[i] = H;
        float4 P = ((const float4*)g_P)[i];
        float4 E = ((const float4*)g_E)[i];
        H.x = P.x * H.x + E.x;  H.y = P.y * H.y + E.y;
        H.z = P.z * H.z + E.z;  H.w = P.w * H.w + E.w;
    }
}

// ---------------- K4: re-scan with carry, y = C * h (float4) ---------------
__global__ __launch_bounds__(128)
void scan_apply_kernel()
{
    int h4 = blockIdx.y * 128 + threadIdx.x;
    int c  = blockIdx.x;
    const float4* A4 = (const float4*)g_Abar;
    const float4* B4 = (const float4*)g_Bx;
    const float4* C4 = (const float4*)g_C;
    float4* Y4 = (float4*)g_y;
    float4 H = ((const float4*)g_carry)[(size_t)c * (HIDN / 4) + h4];
    size_t base = (size_t)c * CH * (HIDN / 4) + h4;
#pragma unroll 4
    for (int i = 0; i < CH; i++) {
        size_t idx = base + (size_t)i * (HIDN / 4);
        float4 a  = A4[idx];
        float4 bx = B4[idx];
        float4 cc = C4[idx];
        H.x = a.x * H.x + bx.x;  H.y = a.y * H.y + bx.y;
        H.z = a.z * H.z + bx.z;  H.w = a.w * H.w + bx.w;
        Y4[idx] = make_float4(cc.x * H.x, cc.y * H.y, cc.z * H.z, cc.w * H.w);
    }
}

// ---------------- K5: out = y @ W_out^T + b_out + x @ W_skip^T -------------
__global__ __launch_bounds__(256)
void out_kernel(const float* __restrict__ x,
                const float* __restrict__ Wout,
                const float* __restrict__ bout,
                const float* __restrict__ Wskip,
                float* __restrict__ out)
{
    int t  = blockIdx.x;
    int tx = threadIdx.x;
    float p[NOBJN];
#pragma unroll
    for (int j = 0; j < NOBJN; j++) p[j] = 0.f;

    const float4* y4 = (const float4*)(g_y + (size_t)t * HIDN);
#pragma unroll
    for (int it = 0; it < 2; it++) {
        int h4 = tx + it * 256;
        float4 yv = y4[h4];
#pragma unroll
        for (int j = 0; j < NOBJN; j++) {
            float4 w = ((const float4*)(Wout + (size_t)j * HIDN))[h4];
            p[j] += yv.x * w.x + yv.y * w.y + yv.z * w.z + yv.w * w.w;
        }
    }
    if (tx < 128) {
        const float4* x4 = (const float4*)(x + (size_t)t * OBSN);
        float4 xv = x4[tx];
#pragma unroll
        for (int j = 0; j < NOBJN; j++) {
            float4 w = ((const float4*)(Wskip + (size_t)j * OBSN))[tx];
            p[j] += xv.x * w.x + xv.y * w.y + xv.z * w.z + xv.w * w.w;
        }
    }

#pragma unroll
    for (int off = 16; off > 0; off >>= 1)
#pragma unroll
        for (int j = 0; j < NOBJN; j++)
            p[j] += __shfl_xor_sync(0xffffffffu, p[j], off);

    __shared__ float s[NOBJN];
    if (tx < NOBJN) s[tx] = 0.f;
    __syncthreads();
    if ((tx & 31) == 0) {
#pragma unroll
        for (int j = 0; j < NOBJN; j++)
            atomicAdd(&s[j], p[j]);
    }
    __syncthreads();
    if (tx < NOBJN)
        out[(size_t)t * NOBJN + tx] = s[tx] + bout[tx];
}

// ---------------- launch ---------------------------------------------------
extern "C" void kernel_launch(void* const* d_in, const int* in_sizes, int n_in,
                              void* d_out, int out_size)
{
    const float* x     = (const float*)d_in[0];
    const float* Win   = (const float*)d_in[1];
    const float* Wb    = (const float*)d_in[2];
    const float* Wc    = (const float*)d_in[3];
    const float* Wd    = (const float*)d_in[4];
    const float* Alog  = (const float*)d_in[5];
    const float* Wout  = (const float*)d_in[6];
    const float* bout  = (const float*)d_in[7];
    const float* Wskip = (const float*)d_in[8];
    float* out = (float*)d_out;

    __nv_bfloat16 *xh, *xl;
    cudaGetSymbolAddress((void**)&xh, g_xh);
    cudaGetSymbolAddress((void**)&xl, g_xl);

    {
        int n4 = TT * OBSN / 4;
        split_kernel<<<(n4 + 255) / 256, 256>>>(x, xh, xl, n4);
        int w4 = HIDN * OBSN / 4;
        splitw_kernel<<<dim3((w4 + 255) / 256, 4), 256>>>(Win, Wb, Wc, Wd);
    }

    cudaFuncSetAttribute(proj_mma_kernel,
                         cudaFuncAttributeMaxDynamicSharedMemorySize, PROJ_SMEM);
    dim3 g1(HIDN / PN, TT / PM);            // (64, 64)
    proj_mma_kernel<<<g1, 256, PROJ_SMEM>>>(Alog);

    chunk_scan_kernel<<<dim3(NCH, HIDN / 4 / 128), 128>>>();
    chunk_combine_kernel<<<HIDN / 4 / 256, 256>>>();
    scan_apply_kernel<<<dim3(NCH, HIDN / 4 / 128), 128>>>();

    out_kernel<<<TT, 256>>>(x, Wout, bout, Wskip, out);
}